// round 2
// baseline (speedup 1.0000x reference)
#include <cuda_runtime.h>

// CantorAttention: B=2, S=2048, DIM=1024, H=16, HD=64, K=64, DEPTH=8
// Pipeline: qkv = x @ w_qkv^T + b_qkv  -> gathered neighbor attention -> out = attn @ w_out^T + b_out

#define BB   2
#define SS   2048
#define DIM  1024
#define HH   16
#define HD   64
#define KK   64

static __device__ float g_qkv[(long long)BB * SS * 3 * DIM];   // [B,S,3,H,HD] = [4096, 3072]
static __device__ float g_attn[(long long)BB * SS * DIM];      // [B,S,H,HD]  = [4096, 1024]

// ---------------------------------------------------------------------------
// SGEMM with bias: C[M,N] = A[M,K] @ B[N,K]^T + bias[N]
// 128x128 block tile, BK=8, 256 threads, 8x8 per-thread microtile (split 4+4)
// ---------------------------------------------------------------------------
#define BM 128
#define BN 128
#define BK 8

__global__ __launch_bounds__(256)
void sgemm_bias(const float* __restrict__ A, const float* __restrict__ B,
                const float* __restrict__ bias, float* __restrict__ C,
                int M, int N, int Kd)
{
    __shared__ __align__(16) float As[BK][BM];
    __shared__ __align__(16) float Bs[BK][BN];

    const int tid = threadIdx.x;             // 0..255
    const int tx  = tid & 15;                // 0..15
    const int ty  = tid >> 4;                // 0..15
    const int brow = blockIdx.y * BM;
    const int bcol = blockIdx.x * BN;

    // gmem load mapping: 256 threads, each loads one float4 of A and one of B per k-step
    const int lrow = tid >> 1;               // 0..127
    const int lcol = (tid & 1) << 2;         // 0 or 4

    const float* Aptr = A + (size_t)(brow + lrow) * Kd + lcol;
    const float* Bptr = B + (size_t)(bcol + lrow) * Kd + lcol;

    float acc[8][8];
#pragma unroll
    for (int i = 0; i < 8; i++)
#pragma unroll
        for (int j = 0; j < 8; j++) acc[i][j] = 0.0f;

    for (int k0 = 0; k0 < Kd; k0 += BK) {
        float4 av = *(const float4*)(Aptr + k0);
        float4 bv = *(const float4*)(Bptr + k0);
        As[lcol + 0][lrow] = av.x; As[lcol + 1][lrow] = av.y;
        As[lcol + 2][lrow] = av.z; As[lcol + 3][lrow] = av.w;
        Bs[lcol + 0][lrow] = bv.x; Bs[lcol + 1][lrow] = bv.y;
        Bs[lcol + 2][lrow] = bv.z; Bs[lcol + 3][lrow] = bv.w;
        __syncthreads();

#pragma unroll
        for (int kk = 0; kk < BK; kk++) {
            float4 a0 = *(const float4*)&As[kk][ty * 4];
            float4 a1 = *(const float4*)&As[kk][64 + ty * 4];
            float4 b0 = *(const float4*)&Bs[kk][tx * 4];
            float4 b1 = *(const float4*)&Bs[kk][64 + tx * 4];
            const float af[8] = {a0.x, a0.y, a0.z, a0.w, a1.x, a1.y, a1.z, a1.w};
            const float bf[8] = {b0.x, b0.y, b0.z, b0.w, b1.x, b1.y, b1.z, b1.w};
#pragma unroll
            for (int i = 0; i < 8; i++)
#pragma unroll
                for (int j = 0; j < 8; j++)
                    acc[i][j] = fmaf(af[i], bf[j], acc[i][j]);
        }
        __syncthreads();
    }

    // epilogue: add bias, write as float4 (two column groups: tx*4 and 64+tx*4)
#pragma unroll
    for (int i = 0; i < 8; i++) {
        int row = brow + ((i < 4) ? (ty * 4 + i) : (64 + ty * 4 + i - 4));
        float* crow = C + (size_t)row * N + bcol;
        int c0 = tx * 4;
        int c1 = 64 + tx * 4;
        float4 o0, o1;
        o0.x = acc[i][0] + bias[bcol + c0 + 0];
        o0.y = acc[i][1] + bias[bcol + c0 + 1];
        o0.z = acc[i][2] + bias[bcol + c0 + 2];
        o0.w = acc[i][3] + bias[bcol + c0 + 3];
        o1.x = acc[i][4] + bias[bcol + c1 + 0];
        o1.y = acc[i][5] + bias[bcol + c1 + 1];
        o1.z = acc[i][6] + bias[bcol + c1 + 2];
        o1.w = acc[i][7] + bias[bcol + c1 + 3];
        *(float4*)(crow + c0) = o0;
        *(float4*)(crow + c1) = o1;
    }
}

// ---------------------------------------------------------------------------
// Gathered attention: one warp per query (b,h,q).
// Lane d owns head dims {d, d+32}. 8 consecutive queries per block (L1 reuse:
// Cantor routes of nearby positions overlap heavily).
// qkv layout: [B, S, 3, H, HD]
// ---------------------------------------------------------------------------
__global__ __launch_bounds__(256)
void attn_kernel(const int* __restrict__ routes)
{
    const unsigned FULL = 0xffffffffu;
    const int lane = threadIdx.x & 31;
    const int warp = threadIdx.x >> 5;
    const int bh = blockIdx.x >> 8;                 // S/8 = 256 q-blocks per (b,h)
    const int q  = ((blockIdx.x & 255) << 3) | warp;
    const int b  = bh >> 4;
    const int h  = bh & 15;

    const float* qkv = g_qkv;
    const size_t bbase = (size_t)b * SS * 3 * DIM;

    const float* qrow = qkv + bbase + (size_t)q * 3 * DIM + h * HD;
    const float q0 = qrow[lane];
    const float q1 = qrow[lane + 32];

    const int* rt = routes + q * KK;
    const int r0 = rt[lane];
    const int r1 = rt[lane + 32];

    float sc0 = 0.0f, sc1 = 0.0f;
#pragma unroll
    for (int n = 0; n < KK; n++) {
        int rn = __shfl_sync(FULL, (n < 32) ? r0 : r1, n & 31);
        const float* krow = qkv + bbase + (size_t)rn * 3 * DIM + DIM + h * HD;
        float p = q0 * krow[lane] + q1 * krow[lane + 32];
        p += __shfl_xor_sync(FULL, p, 16);
        p += __shfl_xor_sync(FULL, p, 8);
        p += __shfl_xor_sync(FULL, p, 4);
        p += __shfl_xor_sync(FULL, p, 2);
        p += __shfl_xor_sync(FULL, p, 1);
        if ((n & 31) == lane) { if (n < 32) sc0 = p; else sc1 = p; }
    }

    const float SCALE = 0.125f;   // 1/sqrt(64)
    sc0 *= SCALE; sc1 *= SCALE;

    float m = fmaxf(sc0, sc1);
#pragma unroll
    for (int o = 16; o > 0; o >>= 1) m = fmaxf(m, __shfl_xor_sync(FULL, m, o));
    float e0 = __expf(sc0 - m);
    float e1 = __expf(sc1 - m);
    float s = e0 + e1;
#pragma unroll
    for (int o = 16; o > 0; o >>= 1) s += __shfl_xor_sync(FULL, s, o);
    const float inv = 1.0f / s;

    float o0 = 0.0f, o1 = 0.0f;
#pragma unroll
    for (int n = 0; n < KK; n++) {
        float w = __shfl_sync(FULL, (n < 32) ? e0 : e1, n & 31) * inv;
        int rn  = __shfl_sync(FULL, (n < 32) ? r0 : r1, n & 31);
        const float* vrow = qkv + bbase + (size_t)rn * 3 * DIM + 2 * DIM + h * HD;
        o0 = fmaf(w, vrow[lane],      o0);
        o1 = fmaf(w, vrow[lane + 32], o1);
    }

    float* orow = g_attn + (size_t)(b * SS + q) * DIM + h * HD;
    orow[lane]      = o0;
    orow[lane + 32] = o1;
}

// ---------------------------------------------------------------------------
extern "C" void kernel_launch(void* const* d_in, const int* in_sizes, int n_in,
                              void* d_out, int out_size)
{
    const float* x     = (const float*)d_in[0];
    const float* w_qkv = (const float*)d_in[1];
    const float* b_qkv = (const float*)d_in[2];
    const float* w_out = (const float*)d_in[3];
    const float* b_out = (const float*)d_in[4];
    const int*   routes= (const int*)  d_in[5];
    float* out = (float*)d_out;

    float* qkv;  cudaGetSymbolAddress((void**)&qkv,  g_qkv);
    float* attn; cudaGetSymbolAddress((void**)&attn, g_attn);

    const int M = BB * SS;   // 4096

    // 1) qkv = x @ w_qkv^T + b_qkv  : [4096, 3072]
    {
        dim3 grid((3 * DIM) / BN, M / BM);
        sgemm_bias<<<grid, 256>>>(x, w_qkv, b_qkv, qkv, M, 3 * DIM, DIM);
    }

    // 2) gathered attention over Cantor routes
    {
        dim3 grid(BB * HH * (SS / 8));   // 8192 blocks, 8 warps (queries) each
        attn_kernel<<<grid, 256>>>(routes);
    }

    // 3) out = attn @ w_out^T + b_out : [4096, 1024]
    {
        dim3 grid(DIM / BN, M / BM);
        sgemm_bias<<<grid, 256>>>(attn, w_out, b_out, out, M, DIM, DIM);
    }
}

// round 5
// speedup vs baseline: 1.9796x; 1.9796x over previous
#include <cuda_runtime.h>
#include <cuda_bf16.h>
#include <cstdint>

// CantorAttention: B=2, S=2048, DIM=1024, H=16, HD=64, K=64
// GEMMs via legacy mma.sync bf16 (3-product split for fp32 accuracy),
// attention fp32 warp-per-query.

#define BB   2
#define SS   2048
#define DIM  1024
#define HH   16
#define HD   64
#define KK   64
#define MM   (BB * SS)        // 4096
#define KD   1024

// ---------------- scratch ---------------------------------------------------
static __device__ float g_qkv[(size_t)MM * 3 * DIM];
static __device__ float g_attn[(size_t)MM * DIM];
static __device__ __nv_bfloat16 g_xh[(size_t)MM * KD],  g_xl[(size_t)MM * KD];
static __device__ __nv_bfloat16 g_wqh[(size_t)3 * DIM * KD], g_wql[(size_t)3 * DIM * KD];
static __device__ __nv_bfloat16 g_ah[(size_t)MM * KD],  g_al[(size_t)MM * KD];
static __device__ __nv_bfloat16 g_woh[(size_t)DIM * KD], g_wol[(size_t)DIM * KD];

// ---------------- helpers ---------------------------------------------------
__device__ __forceinline__ uint32_t smem_u32(const void* p) {
    uint32_t a;
    asm("{ .reg .u64 t; cvta.to.shared.u64 t, %1; cvt.u32.u64 %0, t; }" : "=r"(a) : "l"(p));
    return a;
}
#define CP_ASYNC16(d, s)  asm volatile("cp.async.cg.shared.global [%0], [%1], 16;" :: "r"(d), "l"(s) : "memory")
#define CP_COMMIT()       asm volatile("cp.async.commit_group;" ::: "memory")
#define CP_WAIT(n)        asm volatile("cp.async.wait_group %0;" :: "n"(n) : "memory")

__device__ __forceinline__ void ldsm_x4(uint32_t* r, uint32_t addr) {
    asm volatile("ldmatrix.sync.aligned.m8n8.x4.shared.b16 {%0,%1,%2,%3}, [%4];"
                 : "=r"(r[0]), "=r"(r[1]), "=r"(r[2]), "=r"(r[3]) : "r"(addr));
}
__device__ __forceinline__ void ldsm_x2(uint32_t* r, uint32_t addr) {
    asm volatile("ldmatrix.sync.aligned.m8n8.x2.shared.b16 {%0,%1}, [%2];"
                 : "=r"(r[0]), "=r"(r[1]) : "r"(addr));
}
__device__ __forceinline__ void mma_bf16(float* d, const uint32_t* a, const uint32_t* b) {
    asm volatile("mma.sync.aligned.m16n8k16.row.col.f32.bf16.bf16.f32 "
                 "{%0,%1,%2,%3}, {%4,%5,%6,%7}, {%8,%9}, {%0,%1,%2,%3};"
                 : "+f"(d[0]), "+f"(d[1]), "+f"(d[2]), "+f"(d[3])
                 : "r"(a[0]), "r"(a[1]), "r"(a[2]), "r"(a[3]), "r"(b[0]), "r"(b[1]));
}

// ---------------- split fp32 -> bf16 hi/lo ----------------------------------
__global__ __launch_bounds__(256)
void split_kernel(const float* __restrict__ in, __nv_bfloat16* __restrict__ hi,
                  __nv_bfloat16* __restrict__ lo, int n4)
{
    int i = blockIdx.x * 256 + threadIdx.x;
    if (i >= n4) return;
    float4 a = ((const float4*)in)[i];
    __nv_bfloat16 h0 = __float2bfloat16(a.x), h1 = __float2bfloat16(a.y);
    __nv_bfloat16 h2 = __float2bfloat16(a.z), h3 = __float2bfloat16(a.w);
    __nv_bfloat162* H = (__nv_bfloat162*)hi;
    __nv_bfloat162* L = (__nv_bfloat162*)lo;
    H[i * 2 + 0] = __nv_bfloat162(h0, h1);
    H[i * 2 + 1] = __nv_bfloat162(h2, h3);
    L[i * 2 + 0] = __nv_bfloat162(__float2bfloat16(a.x - __bfloat162float(h0)),
                                  __float2bfloat16(a.y - __bfloat162float(h1)));
    L[i * 2 + 1] = __nv_bfloat162(__float2bfloat16(a.z - __bfloat162float(h2)),
                                  __float2bfloat16(a.w - __bfloat162float(h3)));
}

// ---------------- mma.sync GEMM: C[M,N] = A @ B^T + bias --------------------
// 128x128 block, BK=32 bf16, 8 warps (warp tile 64x32), 2-stage cp.async.
// smem tile [128][32] bf16, 64B rows, XOR swizzle on 16B units:
//   phys(row,u) = row*64 + ((u ^ ((row>>1)&3))<<4)   (u = 16B unit 0..3)
#define TILE_B  8192                   // one 128x32 bf16 tile
#define STAGE_B (4 * TILE_B)           // Ah, Al, Bh, Bl
#define NCH     (KD / 32)              // 32 chunks

__device__ __forceinline__ uint32_t swz(int row, int u) {
    return (uint32_t)(row * 64 + ((u ^ ((row >> 1) & 3)) << 4));
}

__device__ __forceinline__ void load_stage(
    uint32_t sbase, int s, int chunk, int tm0, int tn0,
    const __nv_bfloat16* Ah, const __nv_bfloat16* Al,
    const __nv_bfloat16* Bh, const __nv_bfloat16* Bl, int tid)
{
    const __nv_bfloat16* srcs[4] = {Ah, Al, Bh, Bl};
    uint32_t st = sbase + s * STAGE_B;
#pragma unroll
    for (int i = 0; i < 8; i++) {
        int id  = tid + (i << 8);          // 0..2047 units of 16B
        int t   = id >> 9;                 // tile 0..3
        int rem = id & 511;
        int row = rem >> 2;
        int u   = rem & 3;
        int g0  = (t < 2) ? tm0 : tn0;
        const __nv_bfloat16* src = srcs[t] + (size_t)(g0 + row) * KD + chunk * 32 + u * 8;
        CP_ASYNC16(st + t * TILE_B + swz(row, u), src);
    }
    CP_COMMIT();
}

__global__ __launch_bounds__(256, 1)
void gemm_mma(const __nv_bfloat16* __restrict__ Ah, const __nv_bfloat16* __restrict__ Al,
              const __nv_bfloat16* __restrict__ Bh, const __nv_bfloat16* __restrict__ Bl,
              const float* __restrict__ bias, float* __restrict__ C, int N)
{
    extern __shared__ __align__(128) char smem[];
    const uint32_t sbase = smem_u32(smem);
    const int tid = threadIdx.x, wid = tid >> 5, lane = tid & 31;
    const int tn0 = blockIdx.x * 128, tm0 = blockIdx.y * 128;
    const int wm = (wid & 1) * 64;     // warp m-offset in tile
    const int wn = (wid >> 1) * 32;    // warp n-offset in tile

    float acc[4][4][4];
#pragma unroll
    for (int i = 0; i < 4; i++)
#pragma unroll
        for (int j = 0; j < 4; j++)
#pragma unroll
            for (int k = 0; k < 4; k++) acc[i][j][k] = 0.0f;

    load_stage(sbase, 0, 0, tm0, tn0, Ah, Al, Bh, Bl, tid);

    for (int c = 0; c < NCH; c++) {
        const uint32_t st = sbase + (c & 1) * STAGE_B;
        if (c + 1 < NCH) {
            load_stage(sbase, (c + 1) & 1, c + 1, tm0, tn0, Ah, Al, Bh, Bl, tid);
            CP_WAIT(1);
        } else {
            CP_WAIT(0);
        }
        __syncthreads();

#pragma unroll
        for (int ks = 0; ks < 2; ks++) {    // two k16 steps per 32-chunk
            // A fragments (hi & lo): rows wm + mt*16 + (lane&15), unit ks*2 + (lane>>4)
            uint32_t a_h[4][4], a_l[4][4];
            {
                const int ar = lane & 15;
                const int au = ks * 2 + (lane >> 4);
#pragma unroll
                for (int mt = 0; mt < 4; mt++) {
                    uint32_t off = swz(wm + mt * 16 + ar, au);
                    ldsm_x4(a_h[mt], st + 0 * TILE_B + off);
                    ldsm_x4(a_l[mt], st + 1 * TILE_B + off);
                }
            }
            // B fragments: rows wn + nt*8 + (lane&7), unit ks*2 + ((lane>>3)&1)
            uint32_t b_h[4][2], b_l[4][2];
            {
                const int br = lane & 7;
                const int bu = ks * 2 + ((lane >> 3) & 1);
#pragma unroll
                for (int nt = 0; nt < 4; nt++) {
                    uint32_t off = swz(wn + nt * 8 + br, bu);
                    ldsm_x2(b_h[nt], st + 2 * TILE_B + off);
                    ldsm_x2(b_l[nt], st + 3 * TILE_B + off);
                }
            }
#pragma unroll
            for (int mt = 0; mt < 4; mt++)
#pragma unroll
                for (int nt = 0; nt < 4; nt++) {
                    mma_bf16(acc[mt][nt], a_h[mt], b_h[nt]);
                    mma_bf16(acc[mt][nt], a_h[mt], b_l[nt]);
                    mma_bf16(acc[mt][nt], a_l[mt], b_h[nt]);
                }
        }
        __syncthreads();
    }

    // epilogue: d0,d1 -> (row, col..col+1), d2,d3 -> (row+8, ...)
    const int erow = tm0 + wm + (lane >> 2);
    const int ecol = tn0 + wn + (lane & 3) * 2;
#pragma unroll
    for (int mt = 0; mt < 4; mt++) {
#pragma unroll
        for (int nt = 0; nt < 4; nt++) {
            int col = ecol + nt * 8;
            float b0 = bias[col], b1 = bias[col + 1];
            float* p0 = C + (size_t)(erow + mt * 16) * N + col;
            float* p1 = C + (size_t)(erow + mt * 16 + 8) * N + col;
            *(float2*)p0 = make_float2(acc[mt][nt][0] + b0, acc[mt][nt][1] + b1);
            *(float2*)p1 = make_float2(acc[mt][nt][2] + b0, acc[mt][nt][3] + b1);
        }
    }
}

// ---------------- gathered attention (fp32, warp per query) -----------------
__global__ __launch_bounds__(256)
void attn_kernel(const int* __restrict__ routes)
{
    const unsigned FULL = 0xffffffffu;
    const int lane = threadIdx.x & 31;
    const int warp = threadIdx.x >> 5;
    const int bh = blockIdx.x >> 8;
    const int q  = ((blockIdx.x & 255) << 3) | warp;
    const int b  = bh >> 4;
    const int h  = bh & 15;

    const float* qkv = g_qkv;
    const size_t bbase = (size_t)b * SS * 3 * DIM;

    const float* qrow = qkv + bbase + (size_t)q * 3 * DIM + h * HD;
    const float q0 = qrow[lane];
    const float q1 = qrow[lane + 32];

    const int* rt = routes + q * KK;
    const int r0 = rt[lane];
    const int r1 = rt[lane + 32];

    float sc0 = 0.0f, sc1 = 0.0f;
#pragma unroll
    for (int n = 0; n < KK; n++) {
        int rn = __shfl_sync(FULL, (n < 32) ? r0 : r1, n & 31);
        const float* krow = qkv + bbase + (size_t)rn * 3 * DIM + DIM + h * HD;
        float p = q0 * krow[lane] + q1 * krow[lane + 32];
        p += __shfl_xor_sync(FULL, p, 16);
        p += __shfl_xor_sync(FULL, p, 8);
        p += __shfl_xor_sync(FULL, p, 4);
        p += __shfl_xor_sync(FULL, p, 2);
        p += __shfl_xor_sync(FULL, p, 1);
        if ((n & 31) == lane) { if (n < 32) sc0 = p; else sc1 = p; }
    }

    const float SCALE = 0.125f;
    sc0 *= SCALE; sc1 *= SCALE;

    float m = fmaxf(sc0, sc1);
#pragma unroll
    for (int o = 16; o > 0; o >>= 1) m = fmaxf(m, __shfl_xor_sync(FULL, m, o));
    float e0 = __expf(sc0 - m);
    float e1 = __expf(sc1 - m);
    float s = e0 + e1;
#pragma unroll
    for (int o = 16; o > 0; o >>= 1) s += __shfl_xor_sync(FULL, s, o);
    const float inv = 1.0f / s;

    float o0 = 0.0f, o1 = 0.0f;
#pragma unroll
    for (int n = 0; n < KK; n++) {
        float w = __shfl_sync(FULL, (n < 32) ? e0 : e1, n & 31) * inv;
        int rn  = __shfl_sync(FULL, (n < 32) ? r0 : r1, n & 31);
        const float* vrow = qkv + bbase + (size_t)rn * 3 * DIM + 2 * DIM + h * HD;
        o0 = fmaf(w, vrow[lane],      o0);
        o1 = fmaf(w, vrow[lane + 32], o1);
    }

    float* orow = g_attn + (size_t)(b * SS + q) * DIM + h * HD;
    orow[lane]      = o0;
    orow[lane + 32] = o1;
}

// ---------------------------------------------------------------------------
extern "C" void kernel_launch(void* const* d_in, const int* in_sizes, int n_in,
                              void* d_out, int out_size)
{
    const float* x     = (const float*)d_in[0];
    const float* w_qkv = (const float*)d_in[1];
    const float* b_qkv = (const float*)d_in[2];
    const float* w_out = (const float*)d_in[3];
    const float* b_out = (const float*)d_in[4];
    const int*   routes= (const int*)  d_in[5];
    float* out = (float*)d_out;

    float *qkv, *attn;
    __nv_bfloat16 *xh, *xl, *wqh, *wql, *ah, *al, *woh, *wol;
    cudaGetSymbolAddress((void**)&qkv,  g_qkv);
    cudaGetSymbolAddress((void**)&attn, g_attn);
    cudaGetSymbolAddress((void**)&xh,  g_xh);  cudaGetSymbolAddress((void**)&xl,  g_xl);
    cudaGetSymbolAddress((void**)&wqh, g_wqh); cudaGetSymbolAddress((void**)&wql, g_wql);
    cudaGetSymbolAddress((void**)&ah,  g_ah);  cudaGetSymbolAddress((void**)&al,  g_al);
    cudaGetSymbolAddress((void**)&woh, g_woh); cudaGetSymbolAddress((void**)&wol, g_wol);

    const int SMEM_TOTAL = 2 * STAGE_B;   // 64 KB
    static int attr_set = 0;
    cudaFuncSetAttribute(gemm_mma, cudaFuncAttributeMaxDynamicSharedMemorySize, SMEM_TOTAL);
    (void)attr_set;

    // splits of GEMM inputs
    {
        int n4 = MM * KD / 4;
        split_kernel<<<(n4 + 255) / 256, 256>>>(x, xh, xl, n4);
        n4 = 3 * DIM * KD / 4;
        split_kernel<<<(n4 + 255) / 256, 256>>>(w_qkv, wqh, wql, n4);
        n4 = DIM * KD / 4;
        split_kernel<<<(n4 + 255) / 256, 256>>>(w_out, woh, wol, n4);
    }

    // 1) qkv = x @ w_qkv^T + b_qkv : [4096, 3072]
    {
        dim3 grid((3 * DIM) / 128, MM / 128);
        gemm_mma<<<grid, 256, SMEM_TOTAL>>>(xh, xl, wqh, wql, b_qkv, qkv, 3 * DIM);
    }

    // 2) gathered attention
    {
        dim3 grid(BB * HH * (SS / 8));
        attn_kernel<<<grid, 256>>>(routes);
    }

    // 3) split attn, out = attn @ w_out^T + b_out : [4096, 1024]
    {
        int n4 = MM * KD / 4;
        split_kernel<<<(n4 + 255) / 256, 256>>>(attn, ah, al, n4);
        dim3 grid(DIM / 128, MM / 128);
        gemm_mma<<<grid, 256, SMEM_TOTAL>>>(ah, al, woh, wol, b_out, out, DIM);
    }
}

// round 6
// speedup vs baseline: 2.2195x; 1.1212x over previous
#include <cuda_runtime.h>
#include <cuda_bf16.h>
#include <cstdint>

// CantorAttention: B=2, S=2048, DIM=1024, H=16, HD=64, K=64
// GEMMs via mma.sync bf16, 3-product split (AhBh+AhBl+AlBh) for fp32 accuracy.

#define BB   2
#define SS   2048
#define DIM  1024
#define HH   16
#define HD   64
#define KK   64
#define MM   (BB * SS)        // 4096
#define KD   1024

// ---------------- scratch ---------------------------------------------------
static __device__ float g_qkv[(size_t)MM * 3 * DIM];
static __device__ float g_attn[(size_t)MM * DIM];
static __device__ __nv_bfloat16 g_xh[(size_t)MM * KD],  g_xl[(size_t)MM * KD];
static __device__ __nv_bfloat16 g_wqh[(size_t)3 * DIM * KD], g_wql[(size_t)3 * DIM * KD];
static __device__ __nv_bfloat16 g_ah[(size_t)MM * KD],  g_al[(size_t)MM * KD];
static __device__ __nv_bfloat16 g_woh[(size_t)DIM * KD], g_wol[(size_t)DIM * KD];

// ---------------- helpers ---------------------------------------------------
__device__ __forceinline__ uint32_t smem_u32(const void* p) {
    uint32_t a;
    asm("{ .reg .u64 t; cvta.to.shared.u64 t, %1; cvt.u32.u64 %0, t; }" : "=r"(a) : "l"(p));
    return a;
}
#define CP_ASYNC16(d, s)  asm volatile("cp.async.cg.shared.global [%0], [%1], 16;" :: "r"(d), "l"(s) : "memory")
#define CP_COMMIT()       asm volatile("cp.async.commit_group;" ::: "memory")
#define CP_WAIT(n)        asm volatile("cp.async.wait_group %0;" :: "n"(n) : "memory")

__device__ __forceinline__ void ldsm_x4(uint32_t* r, uint32_t addr) {
    asm volatile("ldmatrix.sync.aligned.m8n8.x4.shared.b16 {%0,%1,%2,%3}, [%4];"
                 : "=r"(r[0]), "=r"(r[1]), "=r"(r[2]), "=r"(r[3]) : "r"(addr));
}
__device__ __forceinline__ void mma_bf16(float* d, const uint32_t* a, const uint32_t* b) {
    asm volatile("mma.sync.aligned.m16n8k16.row.col.f32.bf16.bf16.f32 "
                 "{%0,%1,%2,%3}, {%4,%5,%6,%7}, {%8,%9}, {%0,%1,%2,%3};"
                 : "+f"(d[0]), "+f"(d[1]), "+f"(d[2]), "+f"(d[3])
                 : "r"(a[0]), "r"(a[1]), "r"(a[2]), "r"(a[3]), "r"(b[0]), "r"(b[1]));
}

// ---------------- split fp32 -> bf16 hi/lo ----------------------------------
__global__ __launch_bounds__(256)
void split_kernel(const float* __restrict__ in, __nv_bfloat16* __restrict__ hi,
                  __nv_bfloat16* __restrict__ lo, int n4)
{
    int i = blockIdx.x * 256 + threadIdx.x;
    if (i >= n4) return;
    float4 a = ((const float4*)in)[i];
    __nv_bfloat16 h0 = __float2bfloat16(a.x), h1 = __float2bfloat16(a.y);
    __nv_bfloat16 h2 = __float2bfloat16(a.z), h3 = __float2bfloat16(a.w);
    __nv_bfloat162* H = (__nv_bfloat162*)hi;
    __nv_bfloat162* L = (__nv_bfloat162*)lo;
    H[i * 2 + 0] = __nv_bfloat162(h0, h1);
    H[i * 2 + 1] = __nv_bfloat162(h2, h3);
    L[i * 2 + 0] = __nv_bfloat162(__float2bfloat16(a.x - __bfloat162float(h0)),
                                  __float2bfloat16(a.y - __bfloat162float(h1)));
    L[i * 2 + 1] = __nv_bfloat162(__float2bfloat16(a.z - __bfloat162float(h2)),
                                  __float2bfloat16(a.w - __bfloat162float(h3)));
}

// ---------------- mma.sync GEMM: C[M,N] = A @ B^T + bias --------------------
// 128x128 block, BK=64 bf16 (128B rows, SW128 swizzle), 8 warps (64x32 warp
// tile), 2-stage cp.async, ping-pong ldmatrix fragments, product-major MMAs.
#define TILE_B  16384                  // one 128x64 bf16 tile (128B rows)
#define STAGE_B (4 * TILE_B)           // Ah, Al, Bh, Bl  (64 KB)
#define NCH     (KD / 64)              // 16 chunks

// SW128: byte = row*128 + u*16  ->  row*128 + ((u ^ (row&7))<<4)
__device__ __forceinline__ uint32_t swz(int row, int u) {
    return (uint32_t)(row * 128 + ((u ^ (row & 7)) << 4));
}

__device__ __forceinline__ void load_stage(
    uint32_t sbase, int s, int chunk, int tm0, int tn0,
    const __nv_bfloat16* Ah, const __nv_bfloat16* Al,
    const __nv_bfloat16* Bh, const __nv_bfloat16* Bl, int tid)
{
    const __nv_bfloat16* srcs[4] = {Ah, Al, Bh, Bl};
    uint32_t st = sbase + s * STAGE_B;
#pragma unroll
    for (int i = 0; i < 16; i++) {
        int id  = tid + (i << 8);          // 0..4095 units of 16B
        int t   = id >> 10;                // tile 0..3
        int rem = id & 1023;
        int row = rem >> 3;                // 0..127
        int u   = rem & 7;                 // 16B unit in 128B row
        int g0  = (t < 2) ? tm0 : tn0;
        const __nv_bfloat16* src = srcs[t] + (size_t)(g0 + row) * KD + chunk * 64 + u * 8;
        CP_ASYNC16(st + t * TILE_B + swz(row, u), src);
    }
    CP_COMMIT();
}

struct Frag {
    uint32_t a_h[4][4], a_l[4][4];   // 4 m-tiles x 4 regs
    uint32_t b_h[4][2], b_l[4][2];   // 4 n-tiles x 2 regs
};

__device__ __forceinline__ void load_frags(Frag& f, uint32_t st, int ks,
                                           int wm, int wn, int lane)
{
    const int ar = lane & 15;
    const int au = ks * 2 + (lane >> 4);
#pragma unroll
    for (int mt = 0; mt < 4; mt++) {
        uint32_t off = swz(wm + mt * 16 + ar, au);
        ldsm_x4(f.a_h[mt], st + 0 * TILE_B + off);
        ldsm_x4(f.a_l[mt], st + 1 * TILE_B + off);
    }
    // B: one x4 covers 2 n-tiles: lanes 0-7 (nt0,k0-7), 8-15 (nt0,k8-15),
    //    16-23 (nt1,k0-7), 24-31 (nt1,k8-15)
    const int br = lane & 7;
    const int bu = ks * 2 + ((lane >> 3) & 1);
    const int bt = (lane >> 4) & 1;
#pragma unroll
    for (int p = 0; p < 2; p++) {
        uint32_t off = swz(wn + (p * 2 + bt) * 8 + br, bu);
        ldsm_x4(&f.b_h[p * 2][0], st + 2 * TILE_B + off);
        ldsm_x4(&f.b_l[p * 2][0], st + 3 * TILE_B + off);
    }
}

__device__ __forceinline__ void mma_all(float (*acc)[4][4], const Frag& f)
{
#pragma unroll
    for (int mt = 0; mt < 4; mt++)
#pragma unroll
        for (int nt = 0; nt < 4; nt++)
            mma_bf16(acc[mt][nt], f.a_h[mt], f.b_h[nt]);
#pragma unroll
    for (int mt = 0; mt < 4; mt++)
#pragma unroll
        for (int nt = 0; nt < 4; nt++)
            mma_bf16(acc[mt][nt], f.a_h[mt], f.b_l[nt]);
#pragma unroll
    for (int mt = 0; mt < 4; mt++)
#pragma unroll
        for (int nt = 0; nt < 4; nt++)
            mma_bf16(acc[mt][nt], f.a_l[mt], f.b_h[nt]);
}

__global__ __launch_bounds__(256, 1)
void gemm_mma(const __nv_bfloat16* __restrict__ Ah, const __nv_bfloat16* __restrict__ Al,
              const __nv_bfloat16* __restrict__ Bh, const __nv_bfloat16* __restrict__ Bl,
              const float* __restrict__ bias, float* __restrict__ C, int N)
{
    extern __shared__ __align__(128) char smem[];
    const uint32_t sbase = smem_u32(smem);
    const int tid = threadIdx.x, wid = tid >> 5, lane = tid & 31;
    const int tn0 = blockIdx.x * 128, tm0 = blockIdx.y * 128;
    const int wm = (wid & 1) * 64;
    const int wn = (wid >> 1) * 32;

    float acc[4][4][4];
#pragma unroll
    for (int i = 0; i < 4; i++)
#pragma unroll
        for (int j = 0; j < 4; j++)
#pragma unroll
            for (int k = 0; k < 4; k++) acc[i][j][k] = 0.0f;

    Frag f0, f1;
    load_stage(sbase, 0, 0, tm0, tn0, Ah, Al, Bh, Bl, tid);

    for (int c = 0; c < NCH; c++) {
        const uint32_t st = sbase + (c & 1) * STAGE_B;
        if (c + 1 < NCH) {
            load_stage(sbase, (c + 1) & 1, c + 1, tm0, tn0, Ah, Al, Bh, Bl, tid);
            CP_WAIT(1);
        } else {
            CP_WAIT(0);
        }
        __syncthreads();

        // 4 k16 steps, ping-pong fragments: L0 L1 M0 L2 M1 L3 M2 M3
        load_frags(f0, st, 0, wm, wn, lane);
        load_frags(f1, st, 1, wm, wn, lane);
        mma_all(acc, f0);
        load_frags(f0, st, 2, wm, wn, lane);
        mma_all(acc, f1);
        load_frags(f1, st, 3, wm, wn, lane);
        mma_all(acc, f0);
        mma_all(acc, f1);

        __syncthreads();
    }

    const int erow = tm0 + wm + (lane >> 2);
    const int ecol = tn0 + wn + (lane & 3) * 2;
#pragma unroll
    for (int mt = 0; mt < 4; mt++) {
#pragma unroll
        for (int nt = 0; nt < 4; nt++) {
            int col = ecol + nt * 8;
            float b0 = bias[col], b1 = bias[col + 1];
            float* p0 = C + (size_t)(erow + mt * 16) * N + col;
            float* p1 = C + (size_t)(erow + mt * 16 + 8) * N + col;
            *(float2*)p0 = make_float2(acc[mt][nt][0] + b0, acc[mt][nt][1] + b1);
            *(float2*)p1 = make_float2(acc[mt][nt][2] + b0, acc[mt][nt][3] + b1);
        }
    }
}

// ---------------- gathered attention (fp32, warp per query) -----------------
// 512 threads = 16 consecutive queries per block (route overlap -> L1 reuse).
__global__ __launch_bounds__(512)
void attn_kernel(const int* __restrict__ routes)
{
    const unsigned FULL = 0xffffffffu;
    const int lane = threadIdx.x & 31;
    const int warp = threadIdx.x >> 5;
    const int bh = blockIdx.x >> 7;                  // SS/16 = 128 blocks per (b,h)
    const int q  = ((blockIdx.x & 127) << 4) | warp;
    const int b  = bh >> 4;
    const int h  = bh & 15;

    const float* qkv = g_qkv;
    const size_t bbase = (size_t)b * SS * 3 * DIM;

    const float* qrow = qkv + bbase + (size_t)q * 3 * DIM + h * HD;
    const float q0 = qrow[lane];
    const float q1 = qrow[lane + 32];

    const int* rt = routes + q * KK;
    const int r0 = rt[lane];
    const int r1 = rt[lane + 32];

    float sc0 = 0.0f, sc1 = 0.0f;
#pragma unroll
    for (int n = 0; n < KK; n++) {
        int rn = __shfl_sync(FULL, (n < 32) ? r0 : r1, n & 31);
        const float* krow = qkv + bbase + (size_t)rn * 3 * DIM + DIM + h * HD;
        float p = q0 * krow[lane] + q1 * krow[lane + 32];
        p += __shfl_xor_sync(FULL, p, 16);
        p += __shfl_xor_sync(FULL, p, 8);
        p += __shfl_xor_sync(FULL, p, 4);
        p += __shfl_xor_sync(FULL, p, 2);
        p += __shfl_xor_sync(FULL, p, 1);
        if ((n & 31) == lane) { if (n < 32) sc0 = p; else sc1 = p; }
    }

    const float SCALE = 0.125f;
    sc0 *= SCALE; sc1 *= SCALE;

    float m = fmaxf(sc0, sc1);
#pragma unroll
    for (int o = 16; o > 0; o >>= 1) m = fmaxf(m, __shfl_xor_sync(FULL, m, o));
    float e0 = __expf(sc0 - m);
    float e1 = __expf(sc1 - m);
    float s = e0 + e1;
#pragma unroll
    for (int o = 16; o > 0; o >>= 1) s += __shfl_xor_sync(FULL, s, o);
    const float inv = 1.0f / s;

    float o0 = 0.0f, o1 = 0.0f;
#pragma unroll
    for (int n = 0; n < KK; n++) {
        float w = __shfl_sync(FULL, (n < 32) ? e0 : e1, n & 31) * inv;
        int rn  = __shfl_sync(FULL, (n < 32) ? r0 : r1, n & 31);
        const float* vrow = qkv + bbase + (size_t)rn * 3 * DIM + 2 * DIM + h * HD;
        o0 = fmaf(w, vrow[lane],      o0);
        o1 = fmaf(w, vrow[lane + 32], o1);
    }

    float* orow = g_attn + (size_t)(b * SS + q) * DIM + h * HD;
    orow[lane]      = o0;
    orow[lane + 32] = o1;
}

// ---------------------------------------------------------------------------
extern "C" void kernel_launch(void* const* d_in, const int* in_sizes, int n_in,
                              void* d_out, int out_size)
{
    const float* x     = (const float*)d_in[0];
    const float* w_qkv = (const float*)d_in[1];
    const float* b_qkv = (const float*)d_in[2];
    const float* w_out = (const float*)d_in[3];
    const float* b_out = (const float*)d_in[4];
    const int*   routes= (const int*)  d_in[5];
    float* out = (float*)d_out;

    float *qkv, *attn;
    __nv_bfloat16 *xh, *xl, *wqh, *wql, *ah, *al, *woh, *wol;
    cudaGetSymbolAddress((void**)&qkv,  g_qkv);
    cudaGetSymbolAddress((void**)&attn, g_attn);
    cudaGetSymbolAddress((void**)&xh,  g_xh);  cudaGetSymbolAddress((void**)&xl,  g_xl);
    cudaGetSymbolAddress((void**)&wqh, g_wqh); cudaGetSymbolAddress((void**)&wql, g_wql);
    cudaGetSymbolAddress((void**)&ah,  g_ah);  cudaGetSymbolAddress((void**)&al,  g_al);
    cudaGetSymbolAddress((void**)&woh, g_woh); cudaGetSymbolAddress((void**)&wol, g_wol);

    const int SMEM_TOTAL = 2 * STAGE_B;   // 128 KB
    cudaFuncSetAttribute(gemm_mma, cudaFuncAttributeMaxDynamicSharedMemorySize, SMEM_TOTAL);

    // splits of GEMM inputs
    {
        int n4 = MM * KD / 4;
        split_kernel<<<(n4 + 255) / 256, 256>>>(x, xh, xl, n4);
        n4 = 3 * DIM * KD / 4;
        split_kernel<<<(n4 + 255) / 256, 256>>>(w_qkv, wqh, wql, n4);
        n4 = DIM * KD / 4;
        split_kernel<<<(n4 + 255) / 256, 256>>>(w_out, woh, wol, n4);
    }

    // 1) qkv = x @ w_qkv^T + b_qkv : [4096, 3072]
    {
        dim3 grid((3 * DIM) / 128, MM / 128);
        gemm_mma<<<grid, 256, SMEM_TOTAL>>>(xh, xl, wqh, wql, b_qkv, qkv, 3 * DIM);
    }

    // 2) gathered attention
    {
        dim3 grid(BB * HH * (SS / 16));
        attn_kernel<<<grid, 512>>>(routes);
    }

    // 3) split attn, out = attn @ w_out^T + b_out : [4096, 1024]
    {
        int n4 = MM * KD / 4;
        split_kernel<<<(n4 + 255) / 256, 256>>>(attn, ah, al, n4);
        dim3 grid(DIM / 128, MM / 128);
        gemm_mma<<<grid, 256, SMEM_TOTAL>>>(ah, al, woh, wol, b_out, out, DIM);
    }
}

// round 8
// speedup vs baseline: 2.2784x; 1.0266x over previous
#include <cuda_runtime.h>
#include <cuda_bf16.h>
#include <cstdint>

// CantorAttention: B=2, S=2048, DIM=1024, H=16, HD=64, K=64
// GEMMs via mma.sync bf16, 3-product split (AhBh+AhBl+AlBh) for fp32 accuracy.
// 3-stage cp.async pipeline; attention fuses bf16 split into its epilogue.

#define BB   2
#define SS   2048
#define DIM  1024
#define HH   16
#define HD   64
#define KK   64
#define MM   (BB * SS)        // 4096
#define KD   1024

// ---------------- scratch ---------------------------------------------------
static __device__ float g_qkv[(size_t)MM * 3 * DIM];
static __device__ __nv_bfloat16 g_xh[(size_t)MM * KD],  g_xl[(size_t)MM * KD];
static __device__ __nv_bfloat16 g_wqh[(size_t)3 * DIM * KD], g_wql[(size_t)3 * DIM * KD];
static __device__ __nv_bfloat16 g_ah[(size_t)MM * KD],  g_al[(size_t)MM * KD];
static __device__ __nv_bfloat16 g_woh[(size_t)DIM * KD], g_wol[(size_t)DIM * KD];

// ---------------- helpers ---------------------------------------------------
__device__ __forceinline__ uint32_t smem_u32(const void* p) {
    uint32_t a;
    asm("{ .reg .u64 t; cvta.to.shared.u64 t, %1; cvt.u32.u64 %0, t; }" : "=r"(a) : "l"(p));
    return a;
}
#define CP_ASYNC16(d, s)  asm volatile("cp.async.cg.shared.global [%0], [%1], 16;" :: "r"(d), "l"(s) : "memory")
#define CP_COMMIT()       asm volatile("cp.async.commit_group;" ::: "memory")
#define CP_WAIT(n)        asm volatile("cp.async.wait_group %0;" :: "n"(n) : "memory")

__device__ __forceinline__ void ldsm_x4(uint32_t* r, uint32_t addr) {
    asm volatile("ldmatrix.sync.aligned.m8n8.x4.shared.b16 {%0,%1,%2,%3}, [%4];"
                 : "=r"(r[0]), "=r"(r[1]), "=r"(r[2]), "=r"(r[3]) : "r"(addr));
}
__device__ __forceinline__ void mma_bf16(float* d, const uint32_t* a, const uint32_t* b) {
    asm volatile("mma.sync.aligned.m16n8k16.row.col.f32.bf16.bf16.f32 "
                 "{%0,%1,%2,%3}, {%4,%5,%6,%7}, {%8,%9}, {%0,%1,%2,%3};"
                 : "+f"(d[0]), "+f"(d[1]), "+f"(d[2]), "+f"(d[3])
                 : "r"(a[0]), "r"(a[1]), "r"(a[2]), "r"(a[3]), "r"(b[0]), "r"(b[1]));
}

// ---------------- split fp32 -> bf16 hi/lo ----------------------------------
__global__ __launch_bounds__(256)
void split_kernel(const float* __restrict__ in, __nv_bfloat16* __restrict__ hi,
                  __nv_bfloat16* __restrict__ lo, int n4)
{
    int i = blockIdx.x * 256 + threadIdx.x;
    if (i >= n4) return;
    float4 a = ((const float4*)in)[i];
    __nv_bfloat16 h0 = __float2bfloat16(a.x), h1 = __float2bfloat16(a.y);
    __nv_bfloat16 h2 = __float2bfloat16(a.z), h3 = __float2bfloat16(a.w);
    __nv_bfloat162* H = (__nv_bfloat162*)hi;
    __nv_bfloat162* L = (__nv_bfloat162*)lo;
    H[i * 2 + 0] = __nv_bfloat162(h0, h1);
    H[i * 2 + 1] = __nv_bfloat162(h2, h3);
    L[i * 2 + 0] = __nv_bfloat162(__float2bfloat16(a.x - __bfloat162float(h0)),
                                  __float2bfloat16(a.y - __bfloat162float(h1)));
    L[i * 2 + 1] = __nv_bfloat162(__float2bfloat16(a.z - __bfloat162float(h2)),
                                  __float2bfloat16(a.w - __bfloat162float(h3)));
}

// ---------------- mma.sync GEMM: C[M,N] = A @ B^T + bias --------------------
// 128x128 block, BK=64 (128B rows, SW128 swizzle), 8 warps (64x32 warp tile),
// 3-stage cp.async pipeline (one __syncthreads per chunk), frag ping-pong.
#define TILE_B  16384                  // one 128x64 bf16 tile
#define STAGE_B (4 * TILE_B)           // Ah, Al, Bh, Bl  (64 KB)
#define NSTG    3
#define NCH     (KD / 64)              // 16 chunks

__device__ __forceinline__ uint32_t swz(int row, int u) {
    return (uint32_t)(row * 128 + ((u ^ (row & 7)) << 4));
}

__device__ __forceinline__ void load_stage(
    uint32_t sbase, int s, int chunk, int tm0, int tn0,
    const __nv_bfloat16* Ah, const __nv_bfloat16* Al,
    const __nv_bfloat16* Bh, const __nv_bfloat16* Bl, int tid)
{
    const __nv_bfloat16* srcs[4] = {Ah, Al, Bh, Bl};
    uint32_t st = sbase + s * STAGE_B;
#pragma unroll
    for (int i = 0; i < 16; i++) {
        int id  = tid + (i << 8);          // 0..4095 units of 16B
        int t   = id >> 10;                // tile 0..3
        int rem = id & 1023;
        int row = rem >> 3;
        int u   = rem & 7;
        int g0  = (t < 2) ? tm0 : tn0;
        const __nv_bfloat16* src = srcs[t] + (size_t)(g0 + row) * KD + chunk * 64 + u * 8;
        CP_ASYNC16(st + t * TILE_B + swz(row, u), src);
    }
    CP_COMMIT();
}

struct Frag {
    uint32_t a_h[4][4], a_l[4][4];
    uint32_t b_h[4][2], b_l[4][2];
};

__device__ __forceinline__ void load_frags(Frag& f, uint32_t st, int ks,
                                           int wm, int wn, int lane)
{
    const int ar = lane & 15;
    const int au = ks * 2 + (lane >> 4);
#pragma unroll
    for (int mt = 0; mt < 4; mt++) {
        uint32_t off = swz(wm + mt * 16 + ar, au);
        ldsm_x4(f.a_h[mt], st + 0 * TILE_B + off);
        ldsm_x4(f.a_l[mt], st + 1 * TILE_B + off);
    }
    const int br = lane & 7;
    const int bu = ks * 2 + ((lane >> 3) & 1);
    const int bt = (lane >> 4) & 1;
#pragma unroll
    for (int p = 0; p < 2; p++) {
        uint32_t off = swz(wn + (p * 2 + bt) * 8 + br, bu);
        ldsm_x4(&f.b_h[p * 2][0], st + 2 * TILE_B + off);
        ldsm_x4(&f.b_l[p * 2][0], st + 3 * TILE_B + off);
    }
}

__device__ __forceinline__ void mma_all(float (*acc)[4][4], const Frag& f)
{
#pragma unroll
    for (int mt = 0; mt < 4; mt++)
#pragma unroll
        for (int nt = 0; nt < 4; nt++)
            mma_bf16(acc[mt][nt], f.a_h[mt], f.b_h[nt]);
#pragma unroll
    for (int mt = 0; mt < 4; mt++)
#pragma unroll
        for (int nt = 0; nt < 4; nt++)
            mma_bf16(acc[mt][nt], f.a_h[mt], f.b_l[nt]);
#pragma unroll
    for (int mt = 0; mt < 4; mt++)
#pragma unroll
        for (int nt = 0; nt < 4; nt++)
            mma_bf16(acc[mt][nt], f.a_l[mt], f.b_h[nt]);
}

__global__ __launch_bounds__(256, 1)
void gemm_mma(const __nv_bfloat16* __restrict__ Ah, const __nv_bfloat16* __restrict__ Al,
              const __nv_bfloat16* __restrict__ Bh, const __nv_bfloat16* __restrict__ Bl,
              const float* __restrict__ bias, float* __restrict__ C, int N)
{
    extern __shared__ __align__(128) char smem[];
    const uint32_t sbase = smem_u32(smem);
    const int tid = threadIdx.x, wid = tid >> 5, lane = tid & 31;
    const int tn0 = blockIdx.x * 128, tm0 = blockIdx.y * 128;
    const int wm = (wid & 1) * 64;
    const int wn = (wid >> 1) * 32;

    float acc[4][4][4];
#pragma unroll
    for (int i = 0; i < 4; i++)
#pragma unroll
        for (int j = 0; j < 4; j++)
#pragma unroll
            for (int k = 0; k < 4; k++) acc[i][j][k] = 0.0f;

    Frag f0, f1;
    load_stage(sbase, 0, 0, tm0, tn0, Ah, Al, Bh, Bl, tid);
    load_stage(sbase, 1, 1, tm0, tn0, Ah, Al, Bh, Bl, tid);

    int slot = 0;       // slot of chunk c
    int nslot = 2;      // slot for chunk c+2
    for (int c = 0; c < NCH; c++) {
        if (c + 1 < NCH) CP_WAIT(1); else CP_WAIT(0);
        __syncthreads();
        if (c + 2 < NCH)
            load_stage(sbase, nslot, c + 2, tm0, tn0, Ah, Al, Bh, Bl, tid);

        const uint32_t st = sbase + slot * STAGE_B;
        load_frags(f0, st, 0, wm, wn, lane);
        load_frags(f1, st, 1, wm, wn, lane);
        mma_all(acc, f0);
        load_frags(f0, st, 2, wm, wn, lane);
        mma_all(acc, f1);
        load_frags(f1, st, 3, wm, wn, lane);
        mma_all(acc, f0);
        mma_all(acc, f1);

        slot = (slot + 1) % NSTG;
        nslot = (nslot + 1) % NSTG;
    }

    const int erow = tm0 + wm + (lane >> 2);
    const int ecol = tn0 + wn + (lane & 3) * 2;
#pragma unroll
    for (int mt = 0; mt < 4; mt++) {
#pragma unroll
        for (int nt = 0; nt < 4; nt++) {
            int col = ecol + nt * 8;
            float b0 = bias[col], b1 = bias[col + 1];
            float* p0 = C + (size_t)(erow + mt * 16) * N + col;
            float* p1 = C + (size_t)(erow + mt * 16 + 8) * N + col;
            *(float2*)p0 = make_float2(acc[mt][nt][0] + b0, acc[mt][nt][1] + b1);
            *(float2*)p1 = make_float2(acc[mt][nt][2] + b0, acc[mt][nt][3] + b1);
        }
    }
}

// ---------------- gathered attention (fp32, warp per query) -----------------
// Lane owns head dims {2l, 2l+1} (float2 loads). Epilogue writes bf16 hi/lo
// splits directly (feeds GEMM2) — no fp32 attn tensor, no separate split pass.
__global__ __launch_bounds__(512)
void attn_kernel(const int* __restrict__ routes)
{
    const unsigned FULL = 0xffffffffu;
    const int lane = threadIdx.x & 31;
    const int warp = threadIdx.x >> 5;
    const int bh = blockIdx.x >> 7;                  // 128 blocks per (b,h)
    const int q  = ((blockIdx.x & 127) << 4) | warp;
    const int b  = bh >> 4;
    const int h  = bh & 15;

    const float* qkv = g_qkv;
    const size_t bbase = (size_t)b * SS * 3 * DIM;

    const float2 qv = *(const float2*)(qkv + bbase + (size_t)q * 3 * DIM + h * HD + 2 * lane);

    const int* rt = routes + q * KK;
    const int r0 = rt[lane];
    const int r1 = rt[lane + 32];

    float sc0 = 0.0f, sc1 = 0.0f;
#pragma unroll
    for (int n = 0; n < KK; n++) {
        int rn = __shfl_sync(FULL, (n < 32) ? r0 : r1, n & 31);
        const float2 kv = *(const float2*)(qkv + bbase + (size_t)rn * 3 * DIM + DIM + h * HD + 2 * lane);
        float p = qv.x * kv.x + qv.y * kv.y;
        p += __shfl_xor_sync(FULL, p, 16);
        p += __shfl_xor_sync(FULL, p, 8);
        p += __shfl_xor_sync(FULL, p, 4);
        p += __shfl_xor_sync(FULL, p, 2);
        p += __shfl_xor_sync(FULL, p, 1);
        if ((n & 31) == lane) { if (n < 32) sc0 = p; else sc1 = p; }
    }

    const float SCALE = 0.125f;
    sc0 *= SCALE; sc1 *= SCALE;

    float m = fmaxf(sc0, sc1);
#pragma unroll
    for (int o = 16; o > 0; o >>= 1) m = fmaxf(m, __shfl_xor_sync(FULL, m, o));
    float e0 = __expf(sc0 - m);
    float e1 = __expf(sc1 - m);
    float s = e0 + e1;
#pragma unroll
    for (int o = 16; o > 0; o >>= 1) s += __shfl_xor_sync(FULL, s, o);
    const float inv = 1.0f / s;

    float ox = 0.0f, oy = 0.0f;
#pragma unroll
    for (int n = 0; n < KK; n++) {
        float w = __shfl_sync(FULL, (n < 32) ? e0 : e1, n & 31) * inv;
        int rn  = __shfl_sync(FULL, (n < 32) ? r0 : r1, n & 31);
        const float2 vv = *(const float2*)(qkv + bbase + (size_t)rn * 3 * DIM + 2 * DIM + h * HD + 2 * lane);
        ox = fmaf(w, vv.x, ox);
        oy = fmaf(w, vv.y, oy);
    }

    // fused bf16 hi/lo split (feeds GEMM2 A operand)
    const size_t obase = (size_t)(b * SS + q) * DIM + h * HD + 2 * lane;
    __nv_bfloat16 hx = __float2bfloat16(ox), hy = __float2bfloat16(oy);
    *(__nv_bfloat162*)(g_ah + obase) = __nv_bfloat162(hx, hy);
    *(__nv_bfloat162*)(g_al + obase) =
        __nv_bfloat162(__float2bfloat16(ox - __bfloat162float(hx)),
                       __float2bfloat16(oy - __bfloat162float(hy)));
}

// ---------------------------------------------------------------------------
extern "C" void kernel_launch(void* const* d_in, const int* in_sizes, int n_in,
                              void* d_out, int out_size)
{
    const float* x     = (const float*)d_in[0];
    const float* w_qkv = (const float*)d_in[1];
    const float* b_qkv = (const float*)d_in[2];
    const float* w_out = (const float*)d_in[3];
    const float* b_out = (const float*)d_in[4];
    const int*   routes= (const int*)  d_in[5];
    float* out = (float*)d_out;

    float* qkv;
    __nv_bfloat16 *xh, *xl, *wqh, *wql, *ah, *al, *woh, *wol;
    cudaGetSymbolAddress((void**)&qkv,  g_qkv);
    cudaGetSymbolAddress((void**)&xh,  g_xh);  cudaGetSymbolAddress((void**)&xl,  g_xl);
    cudaGetSymbolAddress((void**)&wqh, g_wqh); cudaGetSymbolAddress((void**)&wql, g_wql);
    cudaGetSymbolAddress((void**)&ah,  g_ah);  cudaGetSymbolAddress((void**)&al,  g_al);
    cudaGetSymbolAddress((void**)&woh, g_woh); cudaGetSymbolAddress((void**)&wol, g_wol);

    const int SMEM_TOTAL = NSTG * STAGE_B;   // 192 KB
    cudaFuncSetAttribute(gemm_mma, cudaFuncAttributeMaxDynamicSharedMemorySize, SMEM_TOTAL);

    // splits of GEMM inputs
    {
        int n4 = MM * KD / 4;
        split_kernel<<<(n4 + 255) / 256, 256>>>(x, xh, xl, n4);
        n4 = 3 * DIM * KD / 4;
        split_kernel<<<(n4 + 255) / 256, 256>>>(w_qkv, wqh, wql, n4);
        n4 = DIM * KD / 4;
        split_kernel<<<(n4 + 255) / 256, 256>>>(w_out, woh, wol, n4);
    }

    // 1) qkv = x @ w_qkv^T + b_qkv : [4096, 3072]
    {
        dim3 grid((3 * DIM) / 128, MM / 128);
        gemm_mma<<<grid, 256, SMEM_TOTAL>>>(xh, xl, wqh, wql, b_qkv, qkv, 3 * DIM);
    }

    // 2) gathered attention (writes bf16 hi/lo directly)
    {
        dim3 grid(BB * HH * (SS / 16));
        attn_kernel<<<grid, 512>>>(routes);
    }

    // 3) out = attn @ w_out^T + b_out : [4096, 1024]
    {
        dim3 grid(DIM / 128, MM / 128);
        gemm_mma<<<grid, 256, SMEM_TOTAL>>>(ah, al, woh, wol, b_out, out, DIM);
    }
}